// round 5
// baseline (speedup 1.0000x reference)
#include <cuda_runtime.h>

// Segment mean pooling: x [524288,128] f32, pointer [1025] i32 -> out [1024,128] f32.
//
// Kernel 1: zero out (harness poisons it).
// Kernel 2: 64-row chunks, grid=8192 (~7 waves at occ 8) -> hardware work-
//   stealing across waves smooths per-CTA duration spread (the R4 limiter).
//   Per CTA-uniform segment intersection: 8 row-lane warps accumulate float4
//   partials, smem-reduce 8->1, warp 0 flushes inv-scaled partial via scalar
//   atomicAdd into out. Sum of inv-scaled partials == mean.

#define D_FEAT 128
#define D4 (D_FEAT / 4)     // 32 float4 per row
#define CHUNK 64            // rows per CTA

__global__ __launch_bounds__(256) void zero_out_kernel(float4* __restrict__ out4, int n4)
{
    int i = blockIdx.x * blockDim.x + threadIdx.x;
    if (i < n4) out4[i] = make_float4(0.f, 0.f, 0.f, 0.f);
}

__global__ __launch_bounds__(256) void seg_accum_kernel(
    const float4* __restrict__ x4,
    const int* __restrict__ ptr,
    float* __restrict__ out,
    int n_rows, int n_segs)
{
    const int base = blockIdx.x * CHUNK;
    if (base >= n_rows) return;
    const int cend = min(base + CHUNK, n_rows);
    const int c4 = threadIdx.x & 31;   // float4 column 0..31
    const int r  = threadIdx.x >> 5;   // row lane (warp id) 0..7

    __shared__ float4 sred[8][D4];     // 4 KB

    // First segment overlapping the chunk (CTA-uniform -> broadcast L1 hits).
    int lo = 0, hi = n_segs - 1;
    while (lo < hi) {
        int mid = (lo + hi + 1) >> 1;
        if (__ldg(ptr + mid) <= base) lo = mid; else hi = mid - 1;
    }
    int seg = lo;

    for (;;) {
        const int seg_beg = __ldg(ptr + seg);
        const int seg_end = __ldg(ptr + seg + 1);
        const int s = max(seg_beg, base);
        const int e = min(seg_end, cend);

        float4 acc = make_float4(0.f, 0.f, 0.f, 0.f);
        #pragma unroll 4
        for (int row = s + r; row < e; row += 8) {
            const float4 v = x4[(size_t)row * D4 + c4];
            acc.x += v.x; acc.y += v.y; acc.z += v.z; acc.w += v.w;
        }

        // 8 warp-partials -> 1, then warp 0 flushes scaled partial.
        sred[r][c4] = acc;
        __syncthreads();
        if (r == 0) {
            #pragma unroll
            for (int i = 1; i < 8; i++) {
                const float4 v = sred[i][c4];
                acc.x += v.x; acc.y += v.y; acc.z += v.z; acc.w += v.w;
            }
            const int cnt = seg_end - seg_beg;
            const float inv = 1.0f / (float)(cnt > 0 ? cnt : 1);
            float* o = out + (size_t)seg * D_FEAT + c4 * 4;
            atomicAdd(o + 0, acc.x * inv);
            atomicAdd(o + 1, acc.y * inv);
            atomicAdd(o + 2, acc.z * inv);
            atomicAdd(o + 3, acc.w * inv);
        }
        if (seg_end >= cend) break;
        seg++;
        __syncthreads();   // smem reuse safety before next intersection
    }
}

extern "C" void kernel_launch(void* const* d_in, const int* in_sizes, int n_in,
                              void* d_out, int out_size)
{
    const float4* x4  = (const float4*)d_in[0];
    const int*    ptr = (const int*)d_in[1];
    float*        out = (float*)d_out;

    const int n_rows = in_sizes[0] / D_FEAT;   // 524288
    const int n_segs = in_sizes[1] - 1;        // 1024
    const int out_f4 = out_size / 4;           // 32768

    zero_out_kernel<<<(out_f4 + 255) / 256, 256>>>((float4*)out, out_f4);

    const int n_chunks = (n_rows + CHUNK - 1) / CHUNK;   // 8192
    seg_accum_kernel<<<n_chunks, 256>>>(x4, ptr, out, n_rows, n_segs);
}